// round 2
// baseline (speedup 1.0000x reference)
#include <cuda_runtime.h>

// Problem constants (fixed by setup_inputs)
#define BATCH 8
#define NNODES 512
#define DIM 128
// per-half float4 count: B*N*D/4
#define QHALF (BATCH * NNODES * (DIM / 4))

// Per-batch log_softmax result, broadcast to all nodes in kernel 2.
__device__ float g_ls[BATCH * DIM];

// ---------------------------------------------------------------------------
// Kernel 1: one block per batch (128 threads).
//  - reduce x over nodes -> mean coords
//  - mean_nf = mean_x @ W_init + b_init
//  - r1 = relu(mean_nf @ W1 + b1)
//  - h2 = r1 @ W2 + b2
//  - g_ls[b,:] = log_softmax(h2)
// ---------------------------------------------------------------------------
__global__ void __launch_bounds__(128) gcn_head_kernel(
    const float* __restrict__ x,      // [B, N, 2]
    const float* __restrict__ Wi,     // [2, D]
    const float* __restrict__ bi,     // [D]
    const float* __restrict__ W1,     // [D, D]
    const float* __restrict__ b1,     // [D]
    const float* __restrict__ W2,     // [D, D]
    const float* __restrict__ b2)     // [D]
{
    const int b = blockIdx.x;
    const int tid = threadIdx.x;

    __shared__ float sv[DIM];     // vector being multiplied
    __shared__ float r0[DIM];     // reduction scratch
    __shared__ float r1s[DIM];

    // --- sum x over nodes (512 nodes, 128 threads x 4) ---
    const float2* xb = (const float2*)(x + (size_t)b * NNODES * 2);
    float s0 = 0.f, s1 = 0.f;
    #pragma unroll
    for (int j = 0; j < 4; j++) {
        float2 v = xb[tid + 128 * j];
        s0 += v.x; s1 += v.y;
    }
    r0[tid] = s0; r1s[tid] = s1;
    __syncthreads();
    for (int off = 64; off > 0; off >>= 1) {
        if (tid < off) { r0[tid] += r0[tid + off]; r1s[tid] += r1s[tid + off]; }
        __syncthreads();
    }
    const float m0 = r0[0] * (1.0f / NNODES);
    const float m1 = r1s[0] * (1.0f / NNODES);

    // --- mean node_feature (one element per thread) ---
    float mnf = fmaf(m0, Wi[tid], fmaf(m1, Wi[DIM + tid], bi[tid]));
    __syncthreads();           // r0/r1s reads done before reusing sv region
    sv[tid] = mnf;
    __syncthreads();

    // --- conv1 matvec: acc = mean_nf @ W1 + b1 ; relu ---
    float acc = b1[tid];
    #pragma unroll 8
    for (int k = 0; k < DIM; k++) acc = fmaf(sv[k], W1[k * DIM + tid], acc);
    float r1v = fmaxf(acc, 0.f);
    __syncthreads();
    sv[tid] = r1v;
    __syncthreads();

    // --- conv2 matvec: h2 = r1 @ W2 + b2 ---
    float h = b2[tid];
    #pragma unroll 8
    for (int k = 0; k < DIM; k++) h = fmaf(sv[k], W2[k * DIM + tid], h);

    // --- log_softmax over DIM (across the 128 threads) ---
    r0[tid] = h;
    __syncthreads();
    for (int off = 64; off > 0; off >>= 1) {
        if (tid < off) r0[tid] = fmaxf(r0[tid], r0[tid + off]);
        __syncthreads();
    }
    const float mx = r0[0];
    __syncthreads();
    const float e = expf(h - mx);
    r0[tid] = e;
    __syncthreads();
    for (int off = 64; off > 0; off >>= 1) {
        if (tid < off) r0[tid] += r0[tid + off];
        __syncthreads();
    }
    const float lse = logf(r0[0]);

    g_ls[b * DIM + tid] = h - mx - lse;
}

// ---------------------------------------------------------------------------
// Kernel 2: write both outputs, vectorized float4.
//  out[0 .. B*N*D)          = broadcast of g_ls[b,:]      (update_node_feature)
//  out[B*N*D .. 2*B*N*D)    = x @ W_init + b_init         (node_feature)
// ---------------------------------------------------------------------------
__global__ void __launch_bounds__(256) gcn_write_kernel(
    const float* __restrict__ x,
    const float* __restrict__ Wi,
    const float* __restrict__ bi,
    float* __restrict__ out)
{
    const int idx = blockIdx.x * blockDim.x + threadIdx.x;   // float4 index
    float4* out4 = (float4*)out;

    if (idx < QHALF) {
        // broadcast log_softmax result: b = idx / (N*D/4), d4 = idx % (D/4)
        const int b  = idx >> 14;         // N*D/4 = 16384
        const int d4 = idx & 31;          // D/4 = 32
        out4[idx] = ((const float4*)g_ls)[b * 32 + d4];
    } else if (idx < 2 * QHALF) {
        const int j  = idx - QHALF;
        const int b  = j >> 14;
        const int n  = (j >> 5) & (NNODES - 1);
        const int d4 = j & 31;
        const float2 xv = ((const float2*)x)[b * NNODES + n];
        const float4 w0 = ((const float4*)Wi)[d4];
        const float4 w1 = ((const float4*)Wi)[32 + d4];
        const float4 bb = ((const float4*)bi)[d4];
        float4 r;
        r.x = fmaf(xv.x, w0.x, fmaf(xv.y, w1.x, bb.x));
        r.y = fmaf(xv.x, w0.y, fmaf(xv.y, w1.y, bb.y));
        r.z = fmaf(xv.x, w0.z, fmaf(xv.y, w1.z, bb.z));
        r.w = fmaf(xv.x, w0.w, fmaf(xv.y, w1.w, bb.w));
        out4[idx] = r;
    }
}

extern "C" void kernel_launch(void* const* d_in, const int* in_sizes, int n_in,
                              void* d_out, int out_size) {
    // metadata order: x, W_init, b_init, W1, b1, W2, b2, edge_index
    const float* x  = (const float*)d_in[0];
    const float* Wi = (const float*)d_in[1];
    const float* bi = (const float*)d_in[2];
    const float* W1 = (const float*)d_in[3];
    const float* b1 = (const float*)d_in[4];
    const float* W2 = (const float*)d_in[5];
    const float* b2 = (const float*)d_in[6];
    float* out = (float*)d_out;

    gcn_head_kernel<<<BATCH, 128>>>(x, Wi, bi, W1, b1, W2, b2);

    const int total4 = 2 * QHALF;            // 262144 float4 stores
    gcn_write_kernel<<<(total4 + 255) / 256, 256>>>(x, Wi, bi, out);
}